// round 13
// baseline (speedup 1.0000x reference)
#include <cuda_runtime.h>

#define Nn 150000
#define Ee 4800000
#define NOUT 68
#define NW ((Nn + 31) / 32)
#define CAP68 8192
#define CAP2 131072

// ---------------- device scratch (no allocation allowed) ----------------
__device__ __align__(16) float4 g0v[Nn * 2];   // augmented input features (8 dims)
__device__ __align__(16) float4 g1v[Nn * 2];   // S1sum -> layer-1 mean (masked nodes)
__device__ __align__(16) float4 g2v[Nn * 2];   // S2sum -> layer-2 mean (masked nodes)
__device__ float cnt1f[Nn];       // in-degree as float, counted in scan3 at S2|O
__device__ int   cntv[Nn];        // in-degree at S1|O, counted in passB from l2v
__device__ int   zcv[Nn];         // cold-path: # zero-degree in-neighbors
__device__ float d2v[Nn];         // const-column after 2 aggregations
__device__ int   any_zero;
__device__ unsigned bit1[NW];     // S1 = in-neighbors of rows [0,68)
__device__ unsigned bit2[NW];     // S2 = in-neighbors of (S1 u [0,68))
__device__ int2  l68[CAP68];      // edges with dst < 68
__device__ int   n68;
__device__ int2  l2v[CAP2];       // edges with dst in S1 u [0,68)
__device__ int   n2;
__device__ float Cmat[4 * 27];

__device__ __forceinline__ bool tb1(int v) {
    return (v < NOUT) || ((__ldg(&bit1[v >> 5]) >> (v & 31)) & 1u);
}
__device__ __forceinline__ bool tb2(int v) {
    return (__ldg(&bit2[v >> 5]) >> (v & 31)) & 1u;
}
__device__ __forceinline__ void red_v4(float* addr, float4 v) {
    asm volatile("red.global.add.v4.f32 [%0], {%1,%2,%3,%4};"
                 :: "l"(addr), "f"(v.x), "f"(v.y), "f"(v.z), "f"(v.w)
                 : "memory");
}
__device__ __forceinline__ void red_f32(float* addr, float v) {
    asm volatile("red.global.add.f32 [%0], %1;" :: "l"(addr), "f"(v) : "memory");
}
__device__ __forceinline__ void red_add1(int* addr) {
    asm volatile("red.global.add.s32 [%0], 1;" :: "l"(addr) : "memory");
}

// ---------------- cmat builder: run by one dedicated block of init ------------
__device__ void build_cmat_block(const float* Wl1, const float* Wr1, const float* b1,
                                 const float* Wl2, const float* Wr2, const float* b2,
                                 const float* Wl3, const float* Wr3, const float* b3) {
    __shared__ float T0[9 * 17], T1[9 * 17];
    __shared__ float U0[9 * 17], U1[9 * 17], U2[9 * 17];
    int t = threadIdx.x;
    int r = t / 17, c = t % 17;
    if (t < 9 * 17) {
        float wl, wr;
        if (r < 8) {
            wl = (c < 16) ? Wl1[r * 16 + c] : 0.f;
            wr = (c < 16) ? Wr1[r * 16 + c] : 0.f;
        } else {
            wl = 0.f;
            wr = (c < 16) ? b1[c] : 1.f;
        }
        T0[t] = wr;
        T1[t] = wl;
    }
    __syncthreads();
    if (t < 9 * 17) {
        float a0 = 0.f, a1 = 0.f, a2 = 0.f;
        for (int k = 0; k < 17; k++) {
            float wr2 = (k < 16) ? ((c < 16) ? Wr2[k * 16 + c] : 0.f)
                                 : ((c < 16) ? b2[c] : 1.f);
            float wl2 = (k < 16 && c < 16) ? Wl2[k * 16 + c] : 0.f;
            float t0 = T0[r * 17 + k], t1 = T1[r * 17 + k];
            a0 += t0 * wr2;
            a1 += t1 * wr2 + t0 * wl2;
            a2 += t1 * wl2;
        }
        U0[t] = a0; U1[t] = a1; U2[t] = a2;
    }
    __syncthreads();
    if (t < 27) {
        int rr = t / 3, cc = t % 3;
        float c0 = 0.f, c1 = 0.f, c2 = 0.f, c3 = 0.f;
        for (int k = 0; k < 17; k++) {
            float wr3 = (k < 16) ? Wr3[k * 3 + cc] : b3[cc];
            float wl3 = (k < 16) ? Wl3[k * 3 + cc] : 0.f;
            float u0 = U0[rr * 17 + k], u1 = U1[rr * 17 + k], u2 = U2[rr * 17 + k];
            c0 += u0 * wr3;
            c1 += u1 * wr3 + u0 * wl3;
            c2 += u2 * wr3 + u1 * wl3;
            c3 += u2 * wl3;
        }
        Cmat[0 * 27 + t] = c0;
        Cmat[1 * 27 + t] = c1;
        Cmat[2 * 27 + t] = c2;
        Cmat[3 * 27 + t] = c3;
    }
}

// ---------------- K1: init everything + compute g0 (+cmat in last block) ------
__global__ void init_kernel(const float* __restrict__ x,
                            const float* __restrict__ w_pos,
                            const float* __restrict__ b_pos,
                            const float* __restrict__ Wl1, const float* __restrict__ Wr1,
                            const float* __restrict__ b1,
                            const float* __restrict__ Wl2, const float* __restrict__ Wr2,
                            const float* __restrict__ b2,
                            const float* __restrict__ Wl3, const float* __restrict__ Wr3,
                            const float* __restrict__ b3,
                            int nodeBlocks) {
    if ((int)blockIdx.x == nodeBlocks) {
        build_cmat_block(Wl1, Wr1, b1, Wl2, Wr2, b2, Wl3, Wr3, b3);
        return;
    }
    int i = blockIdx.x * blockDim.x + threadIdx.x;
    if (i >= Nn) return;
    cntv[i] = 0; zcv[i] = 0; cnt1f[i] = 0.f;
    float4 z = make_float4(0.f, 0.f, 0.f, 0.f);
    g1v[i * 2] = z; g1v[i * 2 + 1] = z;
    g2v[i * 2] = z; g2v[i * 2 + 1] = z;
    if (i < NW) { bit1[i] = 0u; bit2[i] = 0u; }
    if (i == 0) { n68 = 0; n2 = 0; any_zero = 0; }
    float fi = (float)i;
    float g[8];
    g[0] = x[i * 3 + 0]; g[1] = x[i * 3 + 1]; g[2] = x[i * 3 + 2];
#pragma unroll
    for (int p = 0; p < 5; p++) g[3 + p] = tanhf(fi * __ldg(&w_pos[p]) + __ldg(&b_pos[p]));
    g0v[i * 2 + 0] = *(float4*)&g[0];
    g0v[i * 2 + 1] = *(float4*)&g[4];
}

// ---------------- K2: scan1 -- mark S1, compact dst<68 edges ------------------
__global__ void scan1(const int* __restrict__ ei) {
    int t = blockIdx.x * blockDim.x + threadIdx.x;
    int base = t * 4;
    if (base >= Ee) return;
    int4 d4 = __ldcg((const int4*)&ei[Ee + base]);
    int dd[4] = { d4.x, d4.y, d4.z, d4.w };
    bool anyhit = (dd[0] < NOUT) | (dd[1] < NOUT) | (dd[2] < NOUT) | (dd[3] < NOUT);
    if (!anyhit) return;
    int4 s4 = __ldcg((const int4*)&ei[base]);
    int ss[4] = { s4.x, s4.y, s4.z, s4.w };
#pragma unroll
    for (int k = 0; k < 4; k++) {
        if (dd[k] < NOUT) {
            int s = ss[k];
            unsigned m = 1u << (s & 31);
            if (!(__ldg(&bit1[s >> 5]) & m)) atomicOr(&bit1[s >> 5], m);
            int p = atomicAdd(&n68, 1);
            if (p < CAP68) l68[p] = make_int2(s, dd[k]);
        }
    }
}

// ---------------- K3: scan2 -- probe bit1 (L1-hot), mark bit2, compact l2v ----
__global__ void scan2(const int* __restrict__ ei) {
    int t = blockIdx.x * blockDim.x + threadIdx.x;
    int base = t * 4;
    if (base >= Ee) return;
    int4 d4 = __ldcg((const int4*)&ei[Ee + base]);
    int dd[4] = { d4.x, d4.y, d4.z, d4.w };
    bool h0 = tb1(dd[0]), h1 = tb1(dd[1]), h2 = tb1(dd[2]), h3 = tb1(dd[3]);
    if (!(h0 | h1 | h2 | h3)) return;
    int4 s4 = __ldcg((const int4*)&ei[base]);
    int ss[4] = { s4.x, s4.y, s4.z, s4.w };
    bool hh[4] = { h0, h1, h2, h3 };
#pragma unroll
    for (int k = 0; k < 4; k++) {
        if (hh[k]) {
            int s = ss[k];
            unsigned m = 1u << (s & 31);
            if (!(__ldg(&bit2[s >> 5]) & m)) atomicOr(&bit2[s >> 5], m);
            int p = atomicAdd(&n2, 1);
            if (p < CAP2) l2v[p] = make_int2(s, dd[k]);
        }
    }
}

// ---------------- K4: scan3 -- single mask: g0 scatter + float count ----------
__global__ void scan3(const int* __restrict__ ei) {
    int t = blockIdx.x * blockDim.x + threadIdx.x;
    int base = t * 4;
    if (base >= Ee) return;
    int4 d4 = __ldcg((const int4*)&ei[Ee + base]);
    int dd[4] = { d4.x, d4.y, d4.z, d4.w };
    bool ff[4];
#pragma unroll
    for (int k = 0; k < 4; k++) ff[k] = tb2(dd[k]) | (dd[k] < NOUT);
    if (!(ff[0] | ff[1] | ff[2] | ff[3])) return;
    int4 s4 = __ldcg((const int4*)&ei[base]);
    int ss[4] = { s4.x, s4.y, s4.z, s4.w };
#pragma unroll
    for (int k = 0; k < 4; k++) {
        if (ff[k]) {
            int s = ss[k], d = dd[k];
            float4 a = __ldcg(&g0v[s * 2]);
            float4 b = __ldcg(&g0v[s * 2 + 1]);
            red_v4((float*)&g1v[d * 2], a);
            red_v4((float*)&g1v[d * 2 + 1], b);
            red_f32(&cnt1f[d], 1.f);
        }
    }
}

// ---------------- K5: norm1 -- g1 mean at bit2|O (divisor = cnt1f) ------------
__global__ void norm1() {
    int i = blockIdx.x * blockDim.x + threadIdx.x;
    if (i >= Nn) return;
    bool b2m = tb2(i);
    if (!(b2m || (i < NOUT))) return;
    float cf = cnt1f[i];
    if (b2m && cf == 0.f) any_zero = 1;
    float inv = 1.f / fmaxf(cf, 1.f);
    float4 a = g1v[i * 2], b = g1v[i * 2 + 1];
    a.x *= inv; a.y *= inv; a.z *= inv; a.w *= inv;
    b.x *= inv; b.y *= inv; b.z *= inv; b.w *= inv;
    g1v[i * 2] = a; g1v[i * 2 + 1] = b;
}

// ---------------- K6: passB -- scatter g1 over l2v + count S1|O degrees -------
__global__ void passB() {
    int i = blockIdx.x * blockDim.x + threadIdx.x;
    if (i >= n2 || i >= CAP2) return;
    int2 e = l2v[i];
    float4 a = __ldg(&g1v[e.x * 2]);
    float4 b = __ldg(&g1v[e.x * 2 + 1]);
    red_v4((float*)&g2v[e.y * 2], a);
    red_v4((float*)&g2v[e.y * 2 + 1], b);
    red_add1(&cntv[e.y]);                 // exact in-degree of dst in S1|O
    if (any_zero) {                       // cold path; cnt1f final & race-free
        if (cnt1f[e.x] == 0.f) atomicAdd(&zcv[e.y], 1);
    }
}

// ---------------- K7: norm2 -- g2 mean + d2 at bit1|O (divisor = cntv) --------
__global__ void norm2() {
    int i = blockIdx.x * blockDim.x + threadIdx.x;
    if (i >= Nn) return;
    if (!tb1(i)) return;
    int c = cntv[i];
    float inv = 1.f / (float)max(c, 1);
    float4 a = g2v[i * 2], b = g2v[i * 2 + 1];
    a.x *= inv; a.y *= inv; a.z *= inv; a.w *= inv;
    b.x *= inv; b.y *= inv; b.z *= inv; b.w *= inv;
    g2v[i * 2] = a; g2v[i * 2 + 1] = b;
    d2v[i] = any_zero ? (float)(c - zcv[i]) / (float)max(c, 1)
                      : ((c > 0) ? 1.f : 0.f);
}

// ---------------- K8: final -- layer-3 aggregate (smem) + combine -------------
__global__ void final_kernel(float* __restrict__ out) {
    __shared__ float acc[NOUT * 9];
    int t = threadIdx.x;
    for (int j = t; j < NOUT * 9; j += 256) acc[j] = 0.f;
    __syncthreads();
    int nn = n68; if (nn > CAP68) nn = CAP68;
    for (int e = t; e < nn; e += 256) {
        int2 ed = l68[e];
        int s = ed.x, d = ed.y;
        float4 a = g2v[s * 2], b = g2v[s * 2 + 1];
        atomicAdd(&acc[d * 9 + 0], a.x);
        atomicAdd(&acc[d * 9 + 1], a.y);
        atomicAdd(&acc[d * 9 + 2], a.z);
        atomicAdd(&acc[d * 9 + 3], a.w);
        atomicAdd(&acc[d * 9 + 4], b.x);
        atomicAdd(&acc[d * 9 + 5], b.y);
        atomicAdd(&acc[d * 9 + 6], b.z);
        atomicAdd(&acc[d * 9 + 7], b.w);
        atomicAdd(&acc[d * 9 + 8], d2v[s]);
    }
    __syncthreads();
    if (t >= NOUT * 3) return;
    int i = t / 3, c = t % 3;
    const float* g0 = (const float*)g0v;
    const float* g1 = (const float*)g1v;
    const float* g2 = (const float*)g2v;
    int cn = cntv[i];                      // passB-counted; exact for rows < 68
    float inv = 1.f / (float)max(cn, 1);
    float r = 0.f;
#pragma unroll
    for (int f = 0; f < 8; f++) r += g0[i * 8 + f] * Cmat[0 * 27 + f * 3 + c];
    r += Cmat[0 * 27 + 8 * 3 + c];
#pragma unroll
    for (int f = 0; f < 8; f++) r += g1[i * 8 + f] * Cmat[1 * 27 + f * 3 + c];
    r += (cn > 0 ? 1.f : 0.f) * Cmat[1 * 27 + 8 * 3 + c];
#pragma unroll
    for (int f = 0; f < 8; f++) r += g2[i * 8 + f] * Cmat[2 * 27 + f * 3 + c];
    r += d2v[i] * Cmat[2 * 27 + 8 * 3 + c];
#pragma unroll
    for (int f = 0; f < 9; f++) r += acc[i * 9 + f] * inv * Cmat[3 * 27 + f * 3 + c];
    out[t] = r;
}

// ---------------- launch ----------------
extern "C" void kernel_launch(void* const* d_in, const int* in_sizes, int n_in,
                              void* d_out, int out_size) {
    const float* x      = (const float*)d_in[0];
    const int*   ei     = (const int*)d_in[1];
    const float* w_pos  = (const float*)d_in[2];
    const float* b_pos  = (const float*)d_in[3];
    const float* Wl1    = (const float*)d_in[4];
    const float* Wr1    = (const float*)d_in[5];
    const float* b1     = (const float*)d_in[6];
    const float* Wl2    = (const float*)d_in[7];
    const float* Wr2    = (const float*)d_in[8];
    const float* b2     = (const float*)d_in[9];
    const float* Wl3    = (const float*)d_in[10];
    const float* Wr3    = (const float*)d_in[11];
    const float* b3     = (const float*)d_in[12];
    float* out = (float*)d_out;

    int nodeBlocks = (Nn + 255) / 256;
    int edgeBlocks = (Ee / 4 + 255) / 256;

    init_kernel<<<nodeBlocks + 1, 256>>>(x, w_pos, b_pos,
                                         Wl1, Wr1, b1, Wl2, Wr2, b2, Wl3, Wr3, b3,
                                         nodeBlocks);
    scan1<<<edgeBlocks, 256>>>(ei);
    scan2<<<edgeBlocks, 256>>>(ei);
    scan3<<<edgeBlocks, 256>>>(ei);
    norm1<<<nodeBlocks, 256>>>();
    passB<<<(CAP2 + 255) / 256, 256>>>();
    norm2<<<nodeBlocks, 256>>>();
    final_kernel<<<1, 256>>>(out);
}

// round 15
// speedup vs baseline: 1.3131x; 1.3131x over previous
#include <cuda_runtime.h>

#define Nn 150000
#define Ee 4800000
#define NOUT 68
#define NW ((Nn + 31) / 32)
#define CAP68 8192
#define CAP2 131072

// ---------------- device scratch (no allocation allowed) ----------------
__device__ __align__(16) float4 y1v[Nn];   // [g0,1]*C1 per node (xyz; w unused)
__device__ __align__(16) float4 y2v[Nn];   // [g0,1]*C2 per node (xyz; w unused)
__device__ __align__(16) float4 y3v[Nn];   // [g0,1]*C3 per node, w = 1 (count lane)
__device__ __align__(16) float4 a1v[Nn];   // accum M(y3) -> z1 = y2 + M(y3), w=1
__device__ __align__(16) float4 a2v[Nn];   // accum M(z1) -> z2 = y1 + M(z1), w=1
__device__ unsigned bit1[NW];     // S1 = in-neighbors of rows [0,68)
__device__ unsigned bit2[NW];     // S2 = in-neighbors of (S1 u [0,68))
__device__ int2  l68[CAP68];      // edges with dst < 68
__device__ int   n68;
__device__ int2  l2v[CAP2];       // edges with dst in S1 u [0,68)
__device__ int   n2;
__device__ float Cmat[4 * 27];    // C_k[9][3]

__device__ __forceinline__ bool tb1(int v) {
    return (v < NOUT) || ((__ldg(&bit1[v >> 5]) >> (v & 31)) & 1u);
}
__device__ __forceinline__ bool tb2(int v) {
    return (__ldg(&bit2[v >> 5]) >> (v & 31)) & 1u;
}
__device__ __forceinline__ void red_v4(float* addr, float4 v) {
    asm volatile("red.global.add.v4.f32 [%0], {%1,%2,%3,%4};"
                 :: "l"(addr), "f"(v.x), "f"(v.y), "f"(v.z), "f"(v.w)
                 : "memory");
}

// ---------------- K0: collapsed 9x3 weight matrices (unchanged math) ----------
__global__ void build_cmat(const float* __restrict__ Wl1, const float* __restrict__ Wr1,
                           const float* __restrict__ b1,
                           const float* __restrict__ Wl2, const float* __restrict__ Wr2,
                           const float* __restrict__ b2,
                           const float* __restrict__ Wl3, const float* __restrict__ Wr3,
                           const float* __restrict__ b3) {
    __shared__ float T0[9 * 17], T1[9 * 17];
    __shared__ float U0[9 * 17], U1[9 * 17], U2[9 * 17];
    int t = threadIdx.x;
    int r = t / 17, c = t % 17;
    if (t < 9 * 17) {
        float wl, wr;
        if (r < 8) {
            wl = (c < 16) ? Wl1[r * 16 + c] : 0.f;
            wr = (c < 16) ? Wr1[r * 16 + c] : 0.f;
        } else {
            wl = 0.f;
            wr = (c < 16) ? b1[c] : 1.f;
        }
        T0[t] = wr;
        T1[t] = wl;
    }
    __syncthreads();
    if (t < 9 * 17) {
        float a0 = 0.f, a1 = 0.f, a2 = 0.f;
        for (int k = 0; k < 17; k++) {
            float wr2 = (k < 16) ? ((c < 16) ? Wr2[k * 16 + c] : 0.f)
                                 : ((c < 16) ? b2[c] : 1.f);
            float wl2 = (k < 16 && c < 16) ? Wl2[k * 16 + c] : 0.f;
            float t0 = T0[r * 17 + k], t1 = T1[r * 17 + k];
            a0 += t0 * wr2;
            a1 += t1 * wr2 + t0 * wl2;
            a2 += t1 * wl2;
        }
        U0[t] = a0; U1[t] = a1; U2[t] = a2;
    }
    __syncthreads();
    if (t < 27) {
        int rr = t / 3, cc = t % 3;
        float c0 = 0.f, c1 = 0.f, c2 = 0.f, c3 = 0.f;
        for (int k = 0; k < 17; k++) {
            float wr3 = (k < 16) ? Wr3[k * 3 + cc] : b3[cc];
            float wl3 = (k < 16) ? Wl3[k * 3 + cc] : 0.f;
            float u0 = U0[rr * 17 + k], u1 = U1[rr * 17 + k], u2 = U2[rr * 17 + k];
            c0 += u0 * wr3;
            c1 += u1 * wr3 + u0 * wl3;
            c2 += u2 * wr3 + u1 * wl3;
            c3 += u2 * wl3;
        }
        Cmat[0 * 27 + t] = c0;
        Cmat[1 * 27 + t] = c1;
        Cmat[2 * 27 + t] = c2;
        Cmat[3 * 27 + t] = c3;
    }
}

// ---------------- K1: init -- zero accum/bits, compute y1,y2,y3 ---------------
__global__ void init_kernel(const float* __restrict__ x,
                            const float* __restrict__ w_pos,
                            const float* __restrict__ b_pos) {
    int i = blockIdx.x * blockDim.x + threadIdx.x;
    if (i >= Nn) return;
    float4 z = make_float4(0.f, 0.f, 0.f, 0.f);
    a1v[i] = z; a2v[i] = z;
    if (i < NW) { bit1[i] = 0u; bit2[i] = 0u; }
    if (i == 0) { n68 = 0; n2 = 0; }
    float aug[9];
    aug[0] = x[i * 3 + 0]; aug[1] = x[i * 3 + 1]; aug[2] = x[i * 3 + 2];
    float fi = (float)i;
#pragma unroll
    for (int p = 0; p < 5; p++) aug[3 + p] = tanhf(fi * __ldg(&w_pos[p]) + __ldg(&b_pos[p]));
    aug[8] = 1.f;
    float y[3][3];
#pragma unroll
    for (int k = 0; k < 3; k++) {
#pragma unroll
        for (int c = 0; c < 3; c++) {
            float s = 0.f;
#pragma unroll
            for (int f = 0; f < 9; f++) s += aug[f] * __ldg(&Cmat[(k + 1) * 27 + f * 3 + c]);
            y[k][c] = s;
        }
    }
    y1v[i] = make_float4(y[0][0], y[0][1], y[0][2], 0.f);
    y2v[i] = make_float4(y[1][0], y[1][1], y[1][2], 0.f);
    y3v[i] = make_float4(y[2][0], y[2][1], y[2][2], 1.f);   // w=1: count lane
}

// ---------------- K2: scan1 -- mark S1, compact dst<68 edges ------------------
__global__ void scan1(const int* __restrict__ ei) {
    int t = blockIdx.x * blockDim.x + threadIdx.x;
    int base = t * 4;
    if (base >= Ee) return;
    int4 d4 = __ldcg((const int4*)&ei[Ee + base]);
    int dd[4] = { d4.x, d4.y, d4.z, d4.w };
    bool anyhit = (dd[0] < NOUT) | (dd[1] < NOUT) | (dd[2] < NOUT) | (dd[3] < NOUT);
    if (!anyhit) return;
    int4 s4 = __ldcg((const int4*)&ei[base]);
    int ss[4] = { s4.x, s4.y, s4.z, s4.w };
#pragma unroll
    for (int k = 0; k < 4; k++) {
        if (dd[k] < NOUT) {
            int s = ss[k];
            unsigned m = 1u << (s & 31);
            if (!(__ldg(&bit1[s >> 5]) & m)) atomicOr(&bit1[s >> 5], m);
            int p = atomicAdd(&n68, 1);
            if (p < CAP68) l68[p] = make_int2(s, dd[k]);
        }
    }
}

// ---------------- K3: scan2 -- probe bit1, mark bit2, compact l2v -------------
__global__ void scan2(const int* __restrict__ ei) {
    int t = blockIdx.x * blockDim.x + threadIdx.x;
    int base = t * 4;
    if (base >= Ee) return;
    int4 d4 = __ldcg((const int4*)&ei[Ee + base]);
    int dd[4] = { d4.x, d4.y, d4.z, d4.w };
    bool h0 = tb1(dd[0]), h1 = tb1(dd[1]), h2 = tb1(dd[2]), h3 = tb1(dd[3]);
    if (!(h0 | h1 | h2 | h3)) return;
    int4 s4 = __ldcg((const int4*)&ei[base]);
    int ss[4] = { s4.x, s4.y, s4.z, s4.w };
    bool hh[4] = { h0, h1, h2, h3 };
#pragma unroll
    for (int k = 0; k < 4; k++) {
        if (hh[k]) {
            int s = ss[k];
            unsigned m = 1u << (s & 31);
            if (!(__ldg(&bit2[s >> 5]) & m)) atomicOr(&bit2[s >> 5], m);
            int p = atomicAdd(&n2, 1);
            if (p < CAP2) l2v[p] = make_int2(s, dd[k]);
        }
    }
}

// ---------------- K4: scan3 -- masked 16B gather + single red.v4 --------------
__global__ void scan3(const int* __restrict__ ei) {
    int t = blockIdx.x * blockDim.x + threadIdx.x;
    int base = t * 4;
    if (base >= Ee) return;
    int4 d4 = __ldcg((const int4*)&ei[Ee + base]);
    int dd[4] = { d4.x, d4.y, d4.z, d4.w };
    bool ff[4];
#pragma unroll
    for (int k = 0; k < 4; k++) ff[k] = tb2(dd[k]) | (dd[k] < NOUT);
    if (!(ff[0] | ff[1] | ff[2] | ff[3])) return;
    int4 s4 = __ldcg((const int4*)&ei[base]);
    int ss[4] = { s4.x, s4.y, s4.z, s4.w };
#pragma unroll
    for (int k = 0; k < 4; k++) {
        if (ff[k]) {
            float4 p = __ldcg(&y3v[ss[k]]);      // {y3, 1}
            red_v4((float*)&a1v[dd[k]], p);      // sums + count in one op
        }
    }
}

// ---------------- K5: norm1 -- z1 = y2 + M(y3) at S2|O; store w=1 -------------
__global__ void norm1() {
    int i = blockIdx.x * blockDim.x + threadIdx.x;
    if (i >= Nn) return;
    if (!(tb2(i) || (i < NOUT))) return;
    float4 a = a1v[i];
    float inv = 1.f / fmaxf(a.w, 1.f);
    float4 y = y2v[i];
    a1v[i] = make_float4(y.x + a.x * inv, y.y + a.y * inv, y.z + a.z * inv, 1.f);
}

// ---------------- K6: passB -- a2[d] += {z1[s],1} over l2v (~72K edges) -------
__global__ void passB() {
    int i = blockIdx.x * blockDim.x + threadIdx.x;
    if (i >= n2 || i >= CAP2) return;
    int2 e = l2v[i];
    float4 p = __ldg(&a1v[e.x]);
    red_v4((float*)&a2v[e.y], p);
}

// ---------------- K7: norm2 -- z2 = y1 + M(z1) at S1|O; store w=1 -------------
__global__ void norm2() {
    int i = blockIdx.x * blockDim.x + threadIdx.x;
    if (i >= Nn) return;
    if (!tb1(i)) return;
    float4 a = a2v[i];
    float inv = 1.f / fmaxf(a.w, 1.f);
    float4 y = y1v[i];
    a2v[i] = make_float4(y.x + a.x * inv, y.y + a.y * inv, y.z + a.z * inv, 1.f);
}

// ---------------- K8: final -- out = y0 + M(z2) over l68 ----------------------
__global__ void final_kernel(const float* __restrict__ x,
                             const float* __restrict__ w_pos,
                             const float* __restrict__ b_pos,
                             float* __restrict__ out) {
    __shared__ float acc[NOUT * 4];
    int t = threadIdx.x;
    for (int j = t; j < NOUT * 4; j += 256) acc[j] = 0.f;
    __syncthreads();
    int nn = n68; if (nn > CAP68) nn = CAP68;
    for (int e = t; e < nn; e += 256) {
        int2 ed = l68[e];
        float4 p = a2v[ed.x];                    // {z2, 1}
        atomicAdd(&acc[ed.y * 4 + 0], p.x);
        atomicAdd(&acc[ed.y * 4 + 1], p.y);
        atomicAdd(&acc[ed.y * 4 + 2], p.z);
        atomicAdd(&acc[ed.y * 4 + 3], p.w);
    }
    __syncthreads();
    if (t >= NOUT * 3) return;
    int i = t / 3, c = t % 3;
    // y0 = [g0_i, 1] * C0 column c
    float aug[9];
    aug[0] = x[i * 3 + 0]; aug[1] = x[i * 3 + 1]; aug[2] = x[i * 3 + 2];
    float fi = (float)i;
#pragma unroll
    for (int p = 0; p < 5; p++) aug[3 + p] = tanhf(fi * __ldg(&w_pos[p]) + __ldg(&b_pos[p]));
    aug[8] = 1.f;
    float y0 = 0.f;
#pragma unroll
    for (int f = 0; f < 9; f++) y0 += aug[f] * Cmat[0 * 27 + f * 3 + c];
    float inv = 1.f / fmaxf(acc[i * 4 + 3], 1.f);
    out[t] = y0 + acc[i * 4 + c] * inv;
}

// ---------------- launch ----------------
extern "C" void kernel_launch(void* const* d_in, const int* in_sizes, int n_in,
                              void* d_out, int out_size) {
    const float* x      = (const float*)d_in[0];
    const int*   ei     = (const int*)d_in[1];
    const float* w_pos  = (const float*)d_in[2];
    const float* b_pos  = (const float*)d_in[3];
    const float* Wl1    = (const float*)d_in[4];
    const float* Wr1    = (const float*)d_in[5];
    const float* b1     = (const float*)d_in[6];
    const float* Wl2    = (const float*)d_in[7];
    const float* Wr2    = (const float*)d_in[8];
    const float* b2     = (const float*)d_in[9];
    const float* Wl3    = (const float*)d_in[10];
    const float* Wr3    = (const float*)d_in[11];
    const float* b3     = (const float*)d_in[12];
    float* out = (float*)d_out;

    int nodeBlocks = (Nn + 255) / 256;
    int edgeBlocks = (Ee / 4 + 255) / 256;

    build_cmat<<<1, 160>>>(Wl1, Wr1, b1, Wl2, Wr2, b2, Wl3, Wr3, b3);
    init_kernel<<<nodeBlocks, 256>>>(x, w_pos, b_pos);
    scan1<<<edgeBlocks, 256>>>(ei);
    scan2<<<edgeBlocks, 256>>>(ei);
    scan3<<<edgeBlocks, 256>>>(ei);
    norm1<<<nodeBlocks, 256>>>();
    passB<<<(CAP2 + 255) / 256, 256>>>();
    norm2<<<nodeBlocks, 256>>>();
    final_kernel<<<1, 256>>>(x, w_pos, b_pos, out);
}

// round 16
// speedup vs baseline: 1.3257x; 1.0096x over previous
#include <cuda_runtime.h>

#define Nn 150000
#define Ee 4800000
#define NOUT 68
#define NW ((Nn + 31) / 32)
#define CAP68 8192
#define CAP2 131072

// ---------------- device scratch (no allocation allowed) ----------------
__device__ __align__(16) float4 y1v[Nn];   // [g0,1]*C1 per node (xyz; w unused)
__device__ __align__(16) float4 y2v[Nn];   // [g0,1]*C2 per node (xyz; w unused)
__device__ __align__(16) float4 y3v[Nn];   // [g0,1]*C3 per node, w = 1 (count lane)
__device__ __align__(16) float4 a1v[Nn];   // accum M(y3) -> z1 = y2 + M(y3), w=1
__device__ __align__(16) float4 a2v[Nn];   // accum M(z1) -> z2 = y1 + M(z1), w=1
__device__ unsigned bit1[NW];     // S1 = in-neighbors of rows [0,68)
__device__ unsigned bit2[NW];     // S2 = in-neighbors of (S1 u [0,68))
__device__ int2  l68[CAP68];      // edges with dst < 68
__device__ int   n68;
__device__ int2  l2v[CAP2];       // edges with dst in S1 u [0,68)
__device__ int   n2;
__device__ float Cmat[4 * 27];    // C_k[9][3]

__device__ __forceinline__ bool tb1(int v) {
    return (v < NOUT) || ((__ldg(&bit1[v >> 5]) >> (v & 31)) & 1u);
}
__device__ __forceinline__ bool tb2(int v) {
    return (__ldg(&bit2[v >> 5]) >> (v & 31)) & 1u;
}
__device__ __forceinline__ void red_v4(float* addr, float4 v) {
    asm volatile("red.global.add.v4.f32 [%0], {%1,%2,%3,%4};"
                 :: "l"(addr), "f"(v.x), "f"(v.y), "f"(v.z), "f"(v.w)
                 : "memory");
}
__device__ __forceinline__ void red_or(unsigned* addr, unsigned v) {
    asm volatile("red.global.or.b32 [%0], %1;" :: "l"(addr), "r"(v) : "memory");
}

// ---------------- K0: collapsed 9x3 weight matrices (unchanged math) ----------
__global__ void build_cmat(const float* __restrict__ Wl1, const float* __restrict__ Wr1,
                           const float* __restrict__ b1,
                           const float* __restrict__ Wl2, const float* __restrict__ Wr2,
                           const float* __restrict__ b2,
                           const float* __restrict__ Wl3, const float* __restrict__ Wr3,
                           const float* __restrict__ b3) {
    __shared__ float T0[9 * 17], T1[9 * 17];
    __shared__ float U0[9 * 17], U1[9 * 17], U2[9 * 17];
    int t = threadIdx.x;
    int r = t / 17, c = t % 17;
    if (t < 9 * 17) {
        float wl, wr;
        if (r < 8) {
            wl = (c < 16) ? Wl1[r * 16 + c] : 0.f;
            wr = (c < 16) ? Wr1[r * 16 + c] : 0.f;
        } else {
            wl = 0.f;
            wr = (c < 16) ? b1[c] : 1.f;
        }
        T0[t] = wr;
        T1[t] = wl;
    }
    __syncthreads();
    if (t < 9 * 17) {
        float a0 = 0.f, a1 = 0.f, a2 = 0.f;
        for (int k = 0; k < 17; k++) {
            float wr2 = (k < 16) ? ((c < 16) ? Wr2[k * 16 + c] : 0.f)
                                 : ((c < 16) ? b2[c] : 1.f);
            float wl2 = (k < 16 && c < 16) ? Wl2[k * 16 + c] : 0.f;
            float t0 = T0[r * 17 + k], t1 = T1[r * 17 + k];
            a0 += t0 * wr2;
            a1 += t1 * wr2 + t0 * wl2;
            a2 += t1 * wl2;
        }
        U0[t] = a0; U1[t] = a1; U2[t] = a2;
    }
    __syncthreads();
    if (t < 27) {
        int rr = t / 3, cc = t % 3;
        float c0 = 0.f, c1 = 0.f, c2 = 0.f, c3 = 0.f;
        for (int k = 0; k < 17; k++) {
            float wr3 = (k < 16) ? Wr3[k * 3 + cc] : b3[cc];
            float wl3 = (k < 16) ? Wl3[k * 3 + cc] : 0.f;
            float u0 = U0[rr * 17 + k], u1 = U1[rr * 17 + k], u2 = U2[rr * 17 + k];
            c0 += u0 * wr3;
            c1 += u1 * wr3 + u0 * wl3;
            c2 += u2 * wr3 + u1 * wl3;
            c3 += u2 * wl3;
        }
        Cmat[0 * 27 + t] = c0;
        Cmat[1 * 27 + t] = c1;
        Cmat[2 * 27 + t] = c2;
        Cmat[3 * 27 + t] = c3;
    }
}

// ---------------- K1: init -- zero accum/bits, compute y1,y2,y3 ---------------
__global__ void init_kernel(const float* __restrict__ x,
                            const float* __restrict__ w_pos,
                            const float* __restrict__ b_pos) {
    int i = blockIdx.x * blockDim.x + threadIdx.x;
    if (i >= Nn) return;
    float4 z = make_float4(0.f, 0.f, 0.f, 0.f);
    a1v[i] = z; a2v[i] = z;
    if (i < NW) { bit1[i] = 0u; bit2[i] = 0u; }
    if (i == 0) { n68 = 0; n2 = 0; }
    float aug[9];
    aug[0] = x[i * 3 + 0]; aug[1] = x[i * 3 + 1]; aug[2] = x[i * 3 + 2];
    float fi = (float)i;
#pragma unroll
    for (int p = 0; p < 5; p++) aug[3 + p] = tanhf(fi * __ldg(&w_pos[p]) + __ldg(&b_pos[p]));
    aug[8] = 1.f;
    float y[3][3];
#pragma unroll
    for (int k = 0; k < 3; k++) {
#pragma unroll
        for (int c = 0; c < 3; c++) {
            float s = 0.f;
#pragma unroll
            for (int f = 0; f < 9; f++) s += aug[f] * __ldg(&Cmat[(k + 1) * 27 + f * 3 + c]);
            y[k][c] = s;
        }
    }
    y1v[i] = make_float4(y[0][0], y[0][1], y[0][2], 0.f);
    y2v[i] = make_float4(y[1][0], y[1][1], y[1][2], 0.f);
    y3v[i] = make_float4(y[2][0], y[2][1], y[2][2], 1.f);   // w=1: count lane
}

// ---------------- K2: scan1 -- mark S1, compact dst<68 edges ------------------
__global__ void scan1(const int* __restrict__ ei) {
    int t = blockIdx.x * blockDim.x + threadIdx.x;
    int base = t * 4;
    if (base >= Ee) return;
    int4 d4 = __ldcg((const int4*)&ei[Ee + base]);
    int dd[4] = { d4.x, d4.y, d4.z, d4.w };
    bool anyhit = (dd[0] < NOUT) | (dd[1] < NOUT) | (dd[2] < NOUT) | (dd[3] < NOUT);
    if (!anyhit) return;
    int4 s4 = __ldcg((const int4*)&ei[base]);
    int ss[4] = { s4.x, s4.y, s4.z, s4.w };
#pragma unroll
    for (int k = 0; k < 4; k++) {
        if (dd[k] < NOUT) {
            int s = ss[k];
            red_or(&bit1[s >> 5], 1u << (s & 31));
            int p = atomicAdd(&n68, 1);
            if (p < CAP68) l68[p] = make_int2(s, dd[k]);
        }
    }
}

// ---------------- K3: scan2 -- src loaded UPFRONT; probe bit1; mark bit2 ------
__global__ void scan2(const int* __restrict__ ei) {
    int t = blockIdx.x * blockDim.x + threadIdx.x;
    int base = t * 4;
    if (base >= Ee) return;
    // Two independent loads in flight (breaks the dst->probe->src serial chain)
    int4 d4 = __ldcg((const int4*)&ei[Ee + base]);
    int4 s4 = __ldcg((const int4*)&ei[base]);
    int dd[4] = { d4.x, d4.y, d4.z, d4.w };
    int ss[4] = { s4.x, s4.y, s4.z, s4.w };
    bool hh[4];
#pragma unroll
    for (int k = 0; k < 4; k++) hh[k] = tb1(dd[k]);
    if (!(hh[0] | hh[1] | hh[2] | hh[3])) return;
#pragma unroll
    for (int k = 0; k < 4; k++) {
        if (hh[k]) {
            int s = ss[k];
            red_or(&bit2[s >> 5], 1u << (s & 31));   // fire-and-forget mark
            int p = atomicAdd(&n2, 1);
            if (p < CAP2) l2v[p] = make_int2(s, dd[k]);
        }
    }
}

// ---------------- K4: scan3 -- src loaded UPFRONT; masked gather + red.v4 -----
__global__ void scan3(const int* __restrict__ ei) {
    int t = blockIdx.x * blockDim.x + threadIdx.x;
    int base = t * 4;
    if (base >= Ee) return;
    int4 d4 = __ldcg((const int4*)&ei[Ee + base]);
    int4 s4 = __ldcg((const int4*)&ei[base]);
    int dd[4] = { d4.x, d4.y, d4.z, d4.w };
    int ss[4] = { s4.x, s4.y, s4.z, s4.w };
    bool ff[4];
#pragma unroll
    for (int k = 0; k < 4; k++) ff[k] = tb2(dd[k]) | (dd[k] < NOUT);
    if (!(ff[0] | ff[1] | ff[2] | ff[3])) return;
#pragma unroll
    for (int k = 0; k < 4; k++) {
        if (ff[k]) {
            float4 p = __ldcg(&y3v[ss[k]]);      // {y3, 1}
            red_v4((float*)&a1v[dd[k]], p);      // sums + count in one op
        }
    }
}

// ---------------- K5: norm1 -- z1 = y2 + M(y3) at S2|O; store w=1 -------------
__global__ void norm1() {
    int i = blockIdx.x * blockDim.x + threadIdx.x;
    if (i >= Nn) return;
    if (!(tb2(i) || (i < NOUT))) return;
    float4 a = a1v[i];
    float inv = 1.f / fmaxf(a.w, 1.f);
    float4 y = y2v[i];
    a1v[i] = make_float4(y.x + a.x * inv, y.y + a.y * inv, y.z + a.z * inv, 1.f);
}

// ---------------- K6: passB -- a2[d] += {z1[s],1} over l2v (~72K edges) -------
__global__ void passB() {
    int i = blockIdx.x * blockDim.x + threadIdx.x;
    if (i >= n2 || i >= CAP2) return;
    int2 e = l2v[i];
    float4 p = __ldg(&a1v[e.x]);
    red_v4((float*)&a2v[e.y], p);
}

// ---------------- K7: norm2 -- z2 = y1 + M(z1) at S1|O; store w=1 -------------
__global__ void norm2() {
    int i = blockIdx.x * blockDim.x + threadIdx.x;
    if (i >= Nn) return;
    if (!tb1(i)) return;
    float4 a = a2v[i];
    float inv = 1.f / fmaxf(a.w, 1.f);
    float4 y = y1v[i];
    a2v[i] = make_float4(y.x + a.x * inv, y.y + a.y * inv, y.z + a.z * inv, 1.f);
}

// ---------------- K8: final -- out = y0 + M(z2) over l68 ----------------------
__global__ void final_kernel(const float* __restrict__ x,
                             const float* __restrict__ w_pos,
                             const float* __restrict__ b_pos,
                             float* __restrict__ out) {
    __shared__ float acc[NOUT * 4];
    int t = threadIdx.x;
    for (int j = t; j < NOUT * 4; j += 256) acc[j] = 0.f;
    __syncthreads();
    int nn = n68; if (nn > CAP68) nn = CAP68;
    for (int e = t; e < nn; e += 256) {
        int2 ed = l68[e];
        float4 p = a2v[ed.x];                    // {z2, 1}
        atomicAdd(&acc[ed.y * 4 + 0], p.x);
        atomicAdd(&acc[ed.y * 4 + 1], p.y);
        atomicAdd(&acc[ed.y * 4 + 2], p.z);
        atomicAdd(&acc[ed.y * 4 + 3], p.w);
    }
    __syncthreads();
    if (t >= NOUT * 3) return;
    int i = t / 3, c = t % 3;
    // y0 = [g0_i, 1] * C0 column c
    float aug[9];
    aug[0] = x[i * 3 + 0]; aug[1] = x[i * 3 + 1]; aug[2] = x[i * 3 + 2];
    float fi = (float)i;
#pragma unroll
    for (int p = 0; p < 5; p++) aug[3 + p] = tanhf(fi * __ldg(&w_pos[p]) + __ldg(&b_pos[p]));
    aug[8] = 1.f;
    float y0 = 0.f;
#pragma unroll
    for (int f = 0; f < 9; f++) y0 += aug[f] * Cmat[0 * 27 + f * 3 + c];
    float inv = 1.f / fmaxf(acc[i * 4 + 3], 1.f);
    out[t] = y0 + acc[i * 4 + c] * inv;
}

// ---------------- launch ----------------
extern "C" void kernel_launch(void* const* d_in, const int* in_sizes, int n_in,
                              void* d_out, int out_size) {
    const float* x      = (const float*)d_in[0];
    const int*   ei     = (const int*)d_in[1];
    const float* w_pos  = (const float*)d_in[2];
    const float* b_pos  = (const float*)d_in[3];
    const float* Wl1    = (const float*)d_in[4];
    const float* Wr1    = (const float*)d_in[5];
    const float* b1     = (const float*)d_in[6];
    const float* Wl2    = (const float*)d_in[7];
    const float* Wr2    = (const float*)d_in[8];
    const float* b2     = (const float*)d_in[9];
    const float* Wl3    = (const float*)d_in[10];
    const float* Wr3    = (const float*)d_in[11];
    const float* b3     = (const float*)d_in[12];
    float* out = (float*)d_out;

    int nodeBlocks = (Nn + 255) / 256;
    int edgeBlocks = (Ee / 4 + 255) / 256;

    build_cmat<<<1, 160>>>(Wl1, Wr1, b1, Wl2, Wr2, b2, Wl3, Wr3, b3);
    init_kernel<<<nodeBlocks, 256>>>(x, w_pos, b_pos);
    scan1<<<edgeBlocks, 256>>>(ei);
    scan2<<<edgeBlocks, 256>>>(ei);
    scan3<<<edgeBlocks, 256>>>(ei);
    norm1<<<nodeBlocks, 256>>>();
    passB<<<(CAP2 + 255) / 256, 256>>>();
    norm2<<<nodeBlocks, 256>>>();
    final_kernel<<<1, 256>>>(x, w_pos, b_pos, out);
}

// round 17
// speedup vs baseline: 1.8571x; 1.4009x over previous
#include <cuda_runtime.h>

#define Nn 150000
#define Ee 4800000
#define NOUT 68
#define NW ((Nn + 31) / 32)
#define CAP68 8192
#define SEG 64
#define SEGCAP 4096
#define SEGSTRIDE 128          // ints: 512 bytes between counters

// ---------------- device scratch (no allocation allowed) ----------------
__device__ __align__(16) float4 y1v[Nn];   // [g0,1]*C1 per node (xyz; w unused)
__device__ __align__(16) float4 y2v[Nn];   // [g0,1]*C2 per node (xyz; w unused)
__device__ __align__(16) float4 y3v[Nn];   // [g0,1]*C3 per node, w = 1 (count lane)
__device__ __align__(16) float4 a1v[Nn];   // accum M(y3) -> z1 = y2 + M(y3), w=1
__device__ __align__(16) float4 a2v[Nn];   // accum M(z1) -> z2 = y1 + M(z1), w=1
__device__ unsigned bit1[NW];     // S1 = in-neighbors of rows [0,68)
__device__ unsigned bit2[NW];     // S2 = in-neighbors of (S1 u [0,68))
__device__ int2  l68[CAP68];      // edges with dst < 68
__device__ int   n68;
__device__ int2  l2v[SEG * SEGCAP];          // segmented append lists
__device__ int   n2seg[SEG * SEGSTRIDE];     // counters at 512B stride
__device__ float Cmat[4 * 27];    // C_k[9][3]

__device__ __forceinline__ bool tb1(int v) {
    return (v < NOUT) || ((__ldg(&bit1[v >> 5]) >> (v & 31)) & 1u);
}
__device__ __forceinline__ bool tb2(int v) {
    return (__ldg(&bit2[v >> 5]) >> (v & 31)) & 1u;
}
__device__ __forceinline__ void red_v4(float* addr, float4 v) {
    asm volatile("red.global.add.v4.f32 [%0], {%1,%2,%3,%4};"
                 :: "l"(addr), "f"(v.x), "f"(v.y), "f"(v.z), "f"(v.w)
                 : "memory");
}
__device__ __forceinline__ void red_or(unsigned* addr, unsigned v) {
    asm volatile("red.global.or.b32 [%0], %1;" :: "l"(addr), "r"(v) : "memory");
}

// ---------------- K0: collapsed 9x3 weight matrices (unchanged math) ----------
__global__ void build_cmat(const float* __restrict__ Wl1, const float* __restrict__ Wr1,
                           const float* __restrict__ b1,
                           const float* __restrict__ Wl2, const float* __restrict__ Wr2,
                           const float* __restrict__ b2,
                           const float* __restrict__ Wl3, const float* __restrict__ Wr3,
                           const float* __restrict__ b3) {
    __shared__ float T0[9 * 17], T1[9 * 17];
    __shared__ float U0[9 * 17], U1[9 * 17], U2[9 * 17];
    int t = threadIdx.x;
    int r = t / 17, c = t % 17;
    if (t < 9 * 17) {
        float wl, wr;
        if (r < 8) {
            wl = (c < 16) ? Wl1[r * 16 + c] : 0.f;
            wr = (c < 16) ? Wr1[r * 16 + c] : 0.f;
        } else {
            wl = 0.f;
            wr = (c < 16) ? b1[c] : 1.f;
        }
        T0[t] = wr;
        T1[t] = wl;
    }
    __syncthreads();
    if (t < 9 * 17) {
        float a0 = 0.f, a1 = 0.f, a2 = 0.f;
        for (int k = 0; k < 17; k++) {
            float wr2 = (k < 16) ? ((c < 16) ? Wr2[k * 16 + c] : 0.f)
                                 : ((c < 16) ? b2[c] : 1.f);
            float wl2 = (k < 16 && c < 16) ? Wl2[k * 16 + c] : 0.f;
            float t0 = T0[r * 17 + k], t1 = T1[r * 17 + k];
            a0 += t0 * wr2;
            a1 += t1 * wr2 + t0 * wl2;
            a2 += t1 * wl2;
        }
        U0[t] = a0; U1[t] = a1; U2[t] = a2;
    }
    __syncthreads();
    if (t < 27) {
        int rr = t / 3, cc = t % 3;
        float c0 = 0.f, c1 = 0.f, c2 = 0.f, c3 = 0.f;
        for (int k = 0; k < 17; k++) {
            float wr3 = (k < 16) ? Wr3[k * 3 + cc] : b3[cc];
            float wl3 = (k < 16) ? Wl3[k * 3 + cc] : 0.f;
            float u0 = U0[rr * 17 + k], u1 = U1[rr * 17 + k], u2 = U2[rr * 17 + k];
            c0 += u0 * wr3;
            c1 += u1 * wr3 + u0 * wl3;
            c2 += u2 * wr3 + u1 * wl3;
            c3 += u2 * wl3;
        }
        Cmat[0 * 27 + t] = c0;
        Cmat[1 * 27 + t] = c1;
        Cmat[2 * 27 + t] = c2;
        Cmat[3 * 27 + t] = c3;
    }
}

// ---------------- K1: init -- zero accum/bits/counters, compute y1,y2,y3 ------
__global__ void init_kernel(const float* __restrict__ x,
                            const float* __restrict__ w_pos,
                            const float* __restrict__ b_pos) {
    int i = blockIdx.x * blockDim.x + threadIdx.x;
    if (i >= Nn) return;
    float4 z = make_float4(0.f, 0.f, 0.f, 0.f);
    a1v[i] = z; a2v[i] = z;
    if (i < NW) { bit1[i] = 0u; bit2[i] = 0u; }
    if (i < SEG) n2seg[i * SEGSTRIDE] = 0;
    if (i == 0) n68 = 0;
    float aug[9];
    aug[0] = x[i * 3 + 0]; aug[1] = x[i * 3 + 1]; aug[2] = x[i * 3 + 2];
    float fi = (float)i;
#pragma unroll
    for (int p = 0; p < 5; p++) aug[3 + p] = tanhf(fi * __ldg(&w_pos[p]) + __ldg(&b_pos[p]));
    aug[8] = 1.f;
    float y[3][3];
#pragma unroll
    for (int k = 0; k < 3; k++) {
#pragma unroll
        for (int c = 0; c < 3; c++) {
            float s = 0.f;
#pragma unroll
            for (int f = 0; f < 9; f++) s += aug[f] * __ldg(&Cmat[(k + 1) * 27 + f * 3 + c]);
            y[k][c] = s;
        }
    }
    y1v[i] = make_float4(y[0][0], y[0][1], y[0][2], 0.f);
    y2v[i] = make_float4(y[1][0], y[1][1], y[1][2], 0.f);
    y3v[i] = make_float4(y[2][0], y[2][1], y[2][2], 1.f);   // w=1: count lane
}

// ---------------- K2: scan1 -- mark S1, compact dst<68 edges ------------------
__global__ void scan1(const int* __restrict__ ei) {
    int t = blockIdx.x * blockDim.x + threadIdx.x;
    int base = t * 4;
    if (base >= Ee) return;
    int4 d4 = __ldcg((const int4*)&ei[Ee + base]);
    int dd[4] = { d4.x, d4.y, d4.z, d4.w };
    bool anyhit = (dd[0] < NOUT) | (dd[1] < NOUT) | (dd[2] < NOUT) | (dd[3] < NOUT);
    if (!anyhit) return;
    int4 s4 = __ldcg((const int4*)&ei[base]);
    int ss[4] = { s4.x, s4.y, s4.z, s4.w };
#pragma unroll
    for (int k = 0; k < 4; k++) {
        if (dd[k] < NOUT) {
            int s = ss[k];
            red_or(&bit1[s >> 5], 1u << (s & 31));
            int p = atomicAdd(&n68, 1);
            if (p < CAP68) l68[p] = make_int2(s, dd[k]);
        }
    }
}

// ---------------- K3: scan2 -- probe bit1; segmented spread-counter append ----
__global__ void scan2(const int* __restrict__ ei) {
    int t = blockIdx.x * blockDim.x + threadIdx.x;
    int base = t * 4;
    if (base >= Ee) return;
    int4 d4 = __ldcg((const int4*)&ei[Ee + base]);
    int4 s4 = __ldcg((const int4*)&ei[base]);   // independent, issued upfront
    int dd[4] = { d4.x, d4.y, d4.z, d4.w };
    int ss[4] = { s4.x, s4.y, s4.z, s4.w };
    bool hh[4];
#pragma unroll
    for (int k = 0; k < 4; k++) hh[k] = tb1(dd[k]);
    if (!(hh[0] | hh[1] | hh[2] | hh[3])) return;
    int seg = blockIdx.x & (SEG - 1);
#pragma unroll
    for (int k = 0; k < 4; k++) {
        if (hh[k]) {
            int s = ss[k];
            red_or(&bit2[s >> 5], 1u << (s & 31));
            int p = atomicAdd(&n2seg[seg * SEGSTRIDE], 1);
            if (p < SEGCAP) l2v[seg * SEGCAP + p] = make_int2(s, dd[k]);
        }
    }
}

// ---------------- K4: scan3 -- masked 16B gather + single red.v4 --------------
__global__ void scan3(const int* __restrict__ ei) {
    int t = blockIdx.x * blockDim.x + threadIdx.x;
    int base = t * 4;
    if (base >= Ee) return;
    int4 d4 = __ldcg((const int4*)&ei[Ee + base]);
    int4 s4 = __ldcg((const int4*)&ei[base]);
    int dd[4] = { d4.x, d4.y, d4.z, d4.w };
    int ss[4] = { s4.x, s4.y, s4.z, s4.w };
    bool ff[4];
#pragma unroll
    for (int k = 0; k < 4; k++) ff[k] = tb2(dd[k]) | (dd[k] < NOUT);
    if (!(ff[0] | ff[1] | ff[2] | ff[3])) return;
#pragma unroll
    for (int k = 0; k < 4; k++) {
        if (ff[k]) {
            float4 p = __ldcg(&y3v[ss[k]]);      // {y3, 1}
            red_v4((float*)&a1v[dd[k]], p);      // sums + count in one op
        }
    }
}

// ---------------- K5: norm1 -- z1 = y2 + M(y3) at S2|O; store w=1 -------------
__global__ void norm1() {
    int i = blockIdx.x * blockDim.x + threadIdx.x;
    if (i >= Nn) return;
    if (!(tb2(i) || (i < NOUT))) return;
    float4 a = a1v[i];
    float inv = 1.f / fmaxf(a.w, 1.f);
    float4 y = y2v[i];
    a1v[i] = make_float4(y.x + a.x * inv, y.y + a.y * inv, y.z + a.z * inv, 1.f);
}

// ---------------- K6: passB -- a2[d] += {z1[s],1} over segmented l2v ----------
__global__ void passB() {
    int i = blockIdx.x * blockDim.x + threadIdx.x;   // over SEG*SEGCAP
    int seg = i >> 12;                 // SEGCAP = 4096
    int off = i & (SEGCAP - 1);
    int cnt = n2seg[seg * SEGSTRIDE]; if (cnt > SEGCAP) cnt = SEGCAP;
    if (off >= cnt) return;
    int2 e = l2v[i];
    float4 p = __ldg(&a1v[e.x]);
    red_v4((float*)&a2v[e.y], p);
}

// ---------------- K7: norm2 -- z2 = y1 + M(z1) at S1|O; store w=1 -------------
__global__ void norm2() {
    int i = blockIdx.x * blockDim.x + threadIdx.x;
    if (i >= Nn) return;
    if (!tb1(i)) return;
    float4 a = a2v[i];
    float inv = 1.f / fmaxf(a.w, 1.f);
    float4 y = y1v[i];
    a2v[i] = make_float4(y.x + a.x * inv, y.y + a.y * inv, y.z + a.z * inv, 1.f);
}

// ---------------- K8: final -- out = y0 + M(z2) over l68 ----------------------
__global__ void final_kernel(const float* __restrict__ x,
                             const float* __restrict__ w_pos,
                             const float* __restrict__ b_pos,
                             float* __restrict__ out) {
    __shared__ float acc[NOUT * 4];
    int t = threadIdx.x;
    for (int j = t; j < NOUT * 4; j += 256) acc[j] = 0.f;
    __syncthreads();
    int nn = n68; if (nn > CAP68) nn = CAP68;
    for (int e = t; e < nn; e += 256) {
        int2 ed = l68[e];
        float4 p = a2v[ed.x];                    // {z2, 1}
        atomicAdd(&acc[ed.y * 4 + 0], p.x);
        atomicAdd(&acc[ed.y * 4 + 1], p.y);
        atomicAdd(&acc[ed.y * 4 + 2], p.z);
        atomicAdd(&acc[ed.y * 4 + 3], p.w);
    }
    __syncthreads();
    if (t >= NOUT * 3) return;
    int i = t / 3, c = t % 3;
    float aug[9];
    aug[0] = x[i * 3 + 0]; aug[1] = x[i * 3 + 1]; aug[2] = x[i * 3 + 2];
    float fi = (float)i;
#pragma unroll
    for (int p = 0; p < 5; p++) aug[3 + p] = tanhf(fi * __ldg(&w_pos[p]) + __ldg(&b_pos[p]));
    aug[8] = 1.f;
    float y0 = 0.f;
#pragma unroll
    for (int f = 0; f < 9; f++) y0 += aug[f] * Cmat[0 * 27 + f * 3 + c];
    float inv = 1.f / fmaxf(acc[i * 4 + 3], 1.f);
    out[t] = y0 + acc[i * 4 + c] * inv;
}

// ---------------- launch ----------------
extern "C" void kernel_launch(void* const* d_in, const int* in_sizes, int n_in,
                              void* d_out, int out_size) {
    const float* x      = (const float*)d_in[0];
    const int*   ei     = (const int*)d_in[1];
    const float* w_pos  = (const float*)d_in[2];
    const float* b_pos  = (const float*)d_in[3];
    const float* Wl1    = (const float*)d_in[4];
    const float* Wr1    = (const float*)d_in[5];
    const float* b1     = (const float*)d_in[6];
    const float* Wl2    = (const float*)d_in[7];
    const float* Wr2    = (const float*)d_in[8];
    const float* b2     = (const float*)d_in[9];
    const float* Wl3    = (const float*)d_in[10];
    const float* Wr3    = (const float*)d_in[11];
    const float* b3     = (const float*)d_in[12];
    float* out = (float*)d_out;

    int nodeBlocks = (Nn + 255) / 256;
    int edgeBlocks = (Ee / 4 + 255) / 256;
    int segBlocks  = (SEG * SEGCAP) / 256;

    build_cmat<<<1, 160>>>(Wl1, Wr1, b1, Wl2, Wr2, b2, Wl3, Wr3, b3);
    init_kernel<<<nodeBlocks, 256>>>(x, w_pos, b_pos);
    scan1<<<edgeBlocks, 256>>>(ei);
    scan2<<<edgeBlocks, 256>>>(ei);
    scan3<<<edgeBlocks, 256>>>(ei);
    norm1<<<nodeBlocks, 256>>>();
    passB<<<segBlocks, 256>>>();
    norm2<<<nodeBlocks, 256>>>();
    final_kernel<<<1, 256>>>(x, w_pos, b_pos, out);
}